// round 7
// baseline (speedup 1.0000x reference)
#include <cuda_runtime.h>
#include <math.h>

// ---------------------------------------------------------------------------
// Problem constants
// ---------------------------------------------------------------------------
// x: (128, 1, 512, 128) f32 ; patches 16x16 -> n_h=32, n_w=8 -> 256 patches/b
// rfft2(16,16) -> (16,9) = 144 magnitudes; mean -> scalar s per patch.
// out[b,p,e] = (s*u[e] + v[e]) * rsqrt(s^2*A + 2sB + C + eps) * gamma[e] + beta[e]
// with u = colsum(W) - mean, v = b - mean, A=mean(u^2), B=mean(uv), C=mean(v^2).
// ---------------------------------------------------------------------------

#define BATCH 128
#define T_DIM 512
#define F_DIM 128
#define NPATCH 32768          // 128 * 256
#define EMBED 768
#define WROWS 129             // FFT_DIM
#define EPS 1e-5f

// scratch (no allocations allowed)
__device__ float g_s[NPATCH];
__device__ __align__(16) float g_g1[EMBED];   // u[e]*gamma[e]
__device__ __align__(16) float g_g2[EMBED];   // v[e]*gamma[e]
__device__ float g_coef[4];                   // A, B, C

// ---------------------------------------------------------------------------
// 16-point complex FFT (DIT radix-2, fully unrolled, hardcoded twiddles)
// Computes X[k] = sum_n a[n] * exp(-2*pi*i*n*k/16)
// ---------------------------------------------------------------------------
__device__ __forceinline__ float2 cmul(float2 a, float2 b) {
    return make_float2(fmaf(a.x, b.x, -a.y * b.y), fmaf(a.x, b.y, a.y * b.x));
}

__device__ __forceinline__ void fft16(float2* a) {
    // bit-reversal (4-bit)
    float2 t;
    t = a[1];  a[1]  = a[8];  a[8]  = t;
    t = a[2];  a[2]  = a[4];  a[4]  = t;
    t = a[3];  a[3]  = a[12]; a[12] = t;
    t = a[5];  a[5]  = a[10]; a[10] = t;
    t = a[7];  a[7]  = a[14]; a[14] = t;
    t = a[11]; a[11] = a[13]; a[13] = t;

    const float2 W16[8] = {
        { 1.0f,                  0.0f                 },
        { 0.92387953251128674f, -0.38268343236508978f },
        { 0.70710678118654757f, -0.70710678118654757f },
        { 0.38268343236508978f, -0.92387953251128674f },
        { 0.0f,                 -1.0f                 },
        {-0.38268343236508978f, -0.92387953251128674f },
        {-0.70710678118654757f, -0.70710678118654757f },
        {-0.92387953251128674f, -0.38268343236508978f },
    };

    #pragma unroll
    for (int s = 1; s <= 4; s++) {
        const int len  = 1 << s;
        const int half = len >> 1;
        const int step = 16 >> s;
        #pragma unroll
        for (int i = 0; i < 16; i += len) {
            #pragma unroll
            for (int j = 0; j < half; j++) {
                float2 w = W16[j * step];
                float2 tt = cmul(w, a[i + j + half]);
                float2 u  = a[i + j];
                a[i + j]        = make_float2(u.x + tt.x, u.y + tt.y);
                a[i + j + half] = make_float2(u.x - tt.x, u.y - tt.y);
            }
        }
    }
}

// ---------------------------------------------------------------------------
// Kernel 1: per-patch scalar s = mean(log1p(|rfft2(patch)|_ortho))
// 16 threads per patch, 16 patches per block (256 threads).
// Phase 1: thread r does the real FFT-16 of patch row r -> 9 complex.
// Phase 2: threads k<9 do the complex FFT-16 down column k -> 16 magnitudes.
// ---------------------------------------------------------------------------
__global__ __launch_bounds__(256) void s_kernel(const float* __restrict__ x) {
    __shared__ float2 Z[16][9][17];   // [patch][k][row], padded to kill conflicts

    const int tid  = threadIdx.x;
    const int lp   = tid >> 4;        // local patch 0..15
    const int lane = tid & 15;        // 0..15
    const int gp   = blockIdx.x * 16 + lp;    // global patch
    const int bi   = gp >> 8;         // batch
    const int pp   = gp & 255;
    const int h    = pp >> 3;
    const int w    = pp & 7;

    // ---- phase 1: row FFTs ----
    const float* rowp = x + ((size_t)bi * T_DIM + h * 16 + lane) * F_DIM + w * 16;
    const float4* rp4 = reinterpret_cast<const float4*>(rowp);
    float4 v0 = rp4[0], v1 = rp4[1], v2 = rp4[2], v3 = rp4[3];

    float2 a[16];
    a[0]  = make_float2(v0.x, 0.f); a[1]  = make_float2(v0.y, 0.f);
    a[2]  = make_float2(v0.z, 0.f); a[3]  = make_float2(v0.w, 0.f);
    a[4]  = make_float2(v1.x, 0.f); a[5]  = make_float2(v1.y, 0.f);
    a[6]  = make_float2(v1.z, 0.f); a[7]  = make_float2(v1.w, 0.f);
    a[8]  = make_float2(v2.x, 0.f); a[9]  = make_float2(v2.y, 0.f);
    a[10] = make_float2(v2.z, 0.f); a[11] = make_float2(v2.w, 0.f);
    a[12] = make_float2(v3.x, 0.f); a[13] = make_float2(v3.y, 0.f);
    a[14] = make_float2(v3.z, 0.f); a[15] = make_float2(v3.w, 0.f);

    fft16(a);

    #pragma unroll
    for (int k = 0; k < 9; k++)
        Z[lp][k][lane] = a[k];

    __syncthreads();

    // ---- phase 2: column FFTs + log-magnitude sum ----
    float partial = 0.f;
    if (lane < 9) {
        float2 c[16];
        #pragma unroll
        for (int n = 0; n < 16; n++)
            c[n] = Z[lp][lane][n];
        fft16(c);
        #pragma unroll
        for (int n = 0; n < 16; n++) {
            float mag = sqrtf(fmaf(c[n].x, c[n].x, c[n].y * c[n].y)) * 0.0625f;
            partial += log1pf(mag);
        }
    }

    // reduce within the 16-lane group (xor offsets stay inside the group)
    #pragma unroll
    for (int off = 8; off >= 1; off >>= 1)
        partial += __shfl_xor_sync(0xffffffffu, partial, off);

    if (lane == 0)
        g_s[gp] = partial * (1.0f / 144.0f);
}

// ---------------------------------------------------------------------------
// Kernel 2: prep constants (single block, 768 threads)
// ---------------------------------------------------------------------------
__device__ __forceinline__ float block_sum768(float v, float* sh) {
    const int lane = threadIdx.x & 31;
    const int wid  = threadIdx.x >> 5;   // 0..23
    #pragma unroll
    for (int o = 16; o; o >>= 1)
        v += __shfl_xor_sync(0xffffffffu, v, o);
    __syncthreads();                 // protect sh from previous call
    if (lane == 0) sh[wid] = v;
    __syncthreads();
    if (threadIdx.x == 0) {
        float tt = 0.f;
        #pragma unroll
        for (int i = 0; i < 24; i++) tt += sh[i];
        sh[24] = tt;
    }
    __syncthreads();
    return sh[24];
}

__global__ __launch_bounds__(768) void prep_kernel(const float* __restrict__ W,
                                                   const float* __restrict__ b,
                                                   const float* __restrict__ gamma) {
    __shared__ float sh[32];
    const int e = threadIdx.x;

    float wsum = 0.f;
    #pragma unroll 4
    for (int k = 0; k < WROWS; k++)
        wsum += W[k * EMBED + e];
    const float be = b[e];

    const float meanW = block_sum768(wsum, sh) * (1.0f / EMBED);
    const float meanb = block_sum768(be,   sh) * (1.0f / EMBED);

    const float u = wsum - meanW;
    const float v = be   - meanb;

    const float A = block_sum768(u * u, sh) * (1.0f / EMBED);
    const float B = block_sum768(u * v, sh) * (1.0f / EMBED);
    const float C = block_sum768(v * v, sh) * (1.0f / EMBED);

    g_g1[e] = u * gamma[e];
    g_g2[e] = v * gamma[e];
    if (e == 0) {
        g_coef[0] = A; g_coef[1] = B; g_coef[2] = C;
    }
}

// ---------------------------------------------------------------------------
// Kernel 3: write output. 192 threads/block (one float4 column each),
// 8 rows per block -> 4096 blocks. Pure streaming store of 100.7 MB.
// ---------------------------------------------------------------------------
__global__ __launch_bounds__(192) void out_kernel(const float* __restrict__ beta,
                                                  float4* __restrict__ out) {
    const int e4   = threadIdx.x;          // 0..191
    const int row0 = blockIdx.x * 8;

    const float4 G1 = reinterpret_cast<const float4*>(g_g1)[e4];
    const float4 G2 = reinterpret_cast<const float4*>(g_g2)[e4];
    const float4 BE = reinterpret_cast<const float4*>(beta)[e4];
    const float A = g_coef[0], B = g_coef[1], C = g_coef[2];

    #pragma unroll
    for (int r = 0; r < 8; r++) {
        const int row = row0 + r;
        const float s = g_s[row];
        const float inv = rsqrtf(fmaf(fmaf(A, s, 2.0f * B), s, C) + EPS);
        float4 o;
        o.x = fmaf(fmaf(s, G1.x, G2.x), inv, BE.x);
        o.y = fmaf(fmaf(s, G1.y, G2.y), inv, BE.y);
        o.z = fmaf(fmaf(s, G1.z, G2.z), inv, BE.z);
        o.w = fmaf(fmaf(s, G1.w, G2.w), inv, BE.w);
        out[(size_t)row * 192 + e4] = o;
    }
}

// ---------------------------------------------------------------------------
extern "C" void kernel_launch(void* const* d_in, const int* in_sizes, int n_in,
                              void* d_out, int out_size) {
    const float* x     = (const float*)d_in[0];
    const float* W     = (const float*)d_in[1];
    const float* b     = (const float*)d_in[2];
    const float* gamma = (const float*)d_in[3];
    const float* beta  = (const float*)d_in[4];

    s_kernel<<<NPATCH / 16, 256>>>(x);
    prep_kernel<<<1, EMBED>>>(W, b, gamma);
    out_kernel<<<NPATCH / 8, 192>>>(beta, (float4*)d_out);
}

// round 8
// speedup vs baseline: 1.4479x; 1.4479x over previous
#include <cuda_runtime.h>
#include <math.h>

// ---------------------------------------------------------------------------
// x: (128, 1, 512, 128) f32 ; patches 16x16 -> n_h=32, n_w=8 -> 256 patches/b
// rfft2(16,16) -> (16,9) = 144 magnitudes; mean(log1p) -> scalar s per patch.
// out[b,p,e] = (s*u[e] + v[e]) * rsqrt(s^2*A + 2sB + C + eps) * gamma[e] + beta[e]
// with u = colsum(W) - mean, v = b - mean, A=mean(u^2), B=mean(uv), C=mean(v^2).
// ---------------------------------------------------------------------------

#define NPATCH 32768          // 128 * 256
#define EMBED 768
#define WROWS 129             // FFT_DIM
#define EPS 1e-5f

__device__ float g_s[NPATCH];
__device__ __align__(16) float g_g1[EMBED];   // u[e]*gamma[e]
__device__ __align__(16) float g_g2[EMBED];   // v[e]*gamma[e]
__device__ float g_coef[4];                   // A, B, C

// ---------------------------------------------------------------------------
// fast helpers
// ---------------------------------------------------------------------------
__device__ __forceinline__ float fsqrt_approx(float v) {
    float r;
    asm("sqrt.approx.f32 %0, %1;" : "=f"(r) : "f"(v));
    return r;
}

__device__ __forceinline__ float2 cmul(float2 a, float2 b) {
    return make_float2(fmaf(a.x, b.x, -a.y * b.y), fmaf(a.x, b.y, a.y * b.x));
}

// 16-point complex DIT FFT, fully unrolled, twiddles become immediates.
__device__ __forceinline__ void fft16(float2* a) {
    float2 t;
    t = a[1];  a[1]  = a[8];  a[8]  = t;
    t = a[2];  a[2]  = a[4];  a[4]  = t;
    t = a[3];  a[3]  = a[12]; a[12] = t;
    t = a[5];  a[5]  = a[10]; a[10] = t;
    t = a[7];  a[7]  = a[14]; a[14] = t;
    t = a[11]; a[11] = a[13]; a[13] = t;

    const float2 W16[8] = {
        { 1.0f,                  0.0f                 },
        { 0.92387953251128674f, -0.38268343236508978f },
        { 0.70710678118654757f, -0.70710678118654757f },
        { 0.38268343236508978f, -0.92387953251128674f },
        { 0.0f,                 -1.0f                 },
        {-0.38268343236508978f, -0.92387953251128674f },
        {-0.70710678118654757f, -0.70710678118654757f },
        {-0.92387953251128674f, -0.38268343236508978f },
    };

    #pragma unroll
    for (int s = 1; s <= 4; s++) {
        const int len  = 1 << s;
        const int half = len >> 1;
        const int step = 16 >> s;
        #pragma unroll
        for (int i = 0; i < 16; i += len) {
            #pragma unroll
            for (int j = 0; j < half; j++) {
                float2 w  = W16[j * step];
                float2 tt = cmul(w, a[i + j + half]);
                float2 u  = a[i + j];
                a[i + j]        = make_float2(u.x + tt.x, u.y + tt.y);
                a[i + j + half] = make_float2(u.x - tt.x, u.y - tt.y);
            }
        }
    }
}

// ---------------------------------------------------------------------------
// Kernel 1: per-patch scalar s.
// Block = 16 consecutive patches = one contiguous 32-row x 128-col tile of x.
// Stage tile coalesced into swizzled shared, phase-1 row FFTs (lane=row),
// phase-2 column FFTs with a COMPACT 144-thread mapping, then a tiny
// per-patch reduction.
// ---------------------------------------------------------------------------
__device__ __forceinline__ int sw_slot(int tr, int c) {
    // 3-bit XOR swizzle over float4 slots within a 32-slot row
    return tr * 32 + ((c & 24) | ((c ^ tr) & 7));
}

__global__ __launch_bounds__(256, 3) void s_kernel(const float* __restrict__ x) {
    __shared__ float4 st[1024];          // staged 32x128 f32 tile (swizzled)
    __shared__ float2 Z[16][9][17];      // row-FFT outputs [patch][k][row]
    __shared__ float  P[144];            // per-(patch,col) partial sums

    const int tid  = threadIdx.x;
    const int lp   = tid >> 4;           // local patch 0..15
    const int lane = tid & 15;           // 0..15

    // ---- stage: perfectly coalesced tile load ----
    const float4* gx = reinterpret_cast<const float4*>(x) + (size_t)blockIdx.x * 1024;
    #pragma unroll
    for (int k = 0; k < 4; k++) {
        int g  = k * 256 + tid;
        int tr = g >> 5, c = g & 31;
        st[sw_slot(tr, c)] = gx[g];
    }
    __syncthreads();

    // ---- phase 1: row FFTs (thread = one patch row) ----
    {
        const int tr = ((lp >> 3) << 4) + lane;    // tile row
        const int w  = lp & 7;                     // patch col-block
        float2 a[16];
        #pragma unroll
        for (int i = 0; i < 4; i++) {
            float4 v = st[sw_slot(tr, w * 4 + i)];
            a[i * 4 + 0] = make_float2(v.x, 0.f);
            a[i * 4 + 1] = make_float2(v.y, 0.f);
            a[i * 4 + 2] = make_float2(v.z, 0.f);
            a[i * 4 + 3] = make_float2(v.w, 0.f);
        }
        fft16(a);
        #pragma unroll
        for (int k = 0; k < 9; k++)
            Z[lp][k][lane] = a[k];
    }
    __syncthreads();

    // ---- phase 2: column FFTs, compact mapping: t<144 -> (p=t/9, k=t%9) ----
    if (tid < 144) {
        const int p = tid / 9;
        const int k = tid - p * 9;
        float2 c[16];
        #pragma unroll
        for (int n = 0; n < 16; n++)
            c[n] = Z[p][k][n];
        fft16(c);
        float partial = 0.f;
        #pragma unroll
        for (int n = 0; n < 16; n++) {
            float m2  = fmaf(c[n].x, c[n].x, c[n].y * c[n].y);
            float mag = fsqrt_approx(m2) * 0.0625f;   // ortho norm 1/16
            partial  += __logf(1.0f + mag);
        }
        P[tid] = partial;
    }
    __syncthreads();

    // ---- per-patch final reduce (16 threads) ----
    if (tid < 16) {
        float s = 0.f;
        #pragma unroll
        for (int k = 0; k < 9; k++)
            s += P[tid * 9 + k];
        g_s[blockIdx.x * 16 + tid] = s * (1.0f / 144.0f);
    }
}

// ---------------------------------------------------------------------------
// Kernel 2: prep constants (single block, 768 threads)
// ---------------------------------------------------------------------------
__device__ __forceinline__ float block_sum768(float v, float* sh) {
    const int lane = threadIdx.x & 31;
    const int wid  = threadIdx.x >> 5;
    #pragma unroll
    for (int o = 16; o; o >>= 1)
        v += __shfl_xor_sync(0xffffffffu, v, o);
    __syncthreads();
    if (lane == 0) sh[wid] = v;
    __syncthreads();
    if (threadIdx.x == 0) {
        float tt = 0.f;
        #pragma unroll
        for (int i = 0; i < 24; i++) tt += sh[i];
        sh[24] = tt;
    }
    __syncthreads();
    return sh[24];
}

__global__ __launch_bounds__(768) void prep_kernel(const float* __restrict__ W,
                                                   const float* __restrict__ b,
                                                   const float* __restrict__ gamma) {
    __shared__ float sh[32];
    const int e = threadIdx.x;

    float wsum = 0.f;
    #pragma unroll 4
    for (int k = 0; k < WROWS; k++)
        wsum += W[k * EMBED + e];
    const float be = b[e];

    const float meanW = block_sum768(wsum, sh) * (1.0f / EMBED);
    const float meanb = block_sum768(be,   sh) * (1.0f / EMBED);

    const float u = wsum - meanW;
    const float v = be   - meanb;

    const float A = block_sum768(u * u, sh) * (1.0f / EMBED);
    const float B = block_sum768(u * v, sh) * (1.0f / EMBED);
    const float C = block_sum768(v * v, sh) * (1.0f / EMBED);

    g_g1[e] = u * gamma[e];
    g_g2[e] = v * gamma[e];
    if (e == 0) {
        g_coef[0] = A; g_coef[1] = B; g_coef[2] = C;
    }
}

// ---------------------------------------------------------------------------
// Kernel 3: output stream. 192 threads (one float4 column each), 16 rows per
// block -> 2048 blocks. Streaming stores (__stcs) of 100.7 MB.
// ---------------------------------------------------------------------------
__global__ __launch_bounds__(192) void out_kernel(const float* __restrict__ beta,
                                                  float4* __restrict__ out) {
    const int e4   = threadIdx.x;          // 0..191
    const int row0 = blockIdx.x * 16;

    const float4 G1 = reinterpret_cast<const float4*>(g_g1)[e4];
    const float4 G2 = reinterpret_cast<const float4*>(g_g2)[e4];
    const float4 BE = reinterpret_cast<const float4*>(beta)[e4];
    const float A = g_coef[0], B = g_coef[1], C = g_coef[2];

    #pragma unroll
    for (int r = 0; r < 16; r++) {
        const int row = row0 + r;
        const float s = g_s[row];
        const float inv = rsqrtf(fmaf(fmaf(A, s, 2.0f * B), s, C) + EPS);
        float4 o;
        o.x = fmaf(fmaf(s, G1.x, G2.x), inv, BE.x);
        o.y = fmaf(fmaf(s, G1.y, G2.y), inv, BE.y);
        o.z = fmaf(fmaf(s, G1.z, G2.z), inv, BE.z);
        o.w = fmaf(fmaf(s, G1.w, G2.w), inv, BE.w);
        __stcs(&out[(size_t)row * 192 + e4], o);
    }
}

// ---------------------------------------------------------------------------
extern "C" void kernel_launch(void* const* d_in, const int* in_sizes, int n_in,
                              void* d_out, int out_size) {
    const float* x     = (const float*)d_in[0];
    const float* W     = (const float*)d_in[1];
    const float* b     = (const float*)d_in[2];
    const float* gamma = (const float*)d_in[3];
    const float* beta  = (const float*)d_in[4];

    s_kernel<<<NPATCH / 16, 256>>>(x);
    prep_kernel<<<1, EMBED>>>(W, b, gamma);
    out_kernel<<<NPATCH / 16, 192>>>(beta, (float4*)d_out);
}

// round 9
// speedup vs baseline: 1.7548x; 1.2120x over previous
#include <cuda_runtime.h>
#include <math.h>

// ---------------------------------------------------------------------------
// x: (128, 1, 512, 128) f32 ; patches 16x16 -> 256 patches/b, 32768 total.
// rfft2(16,16) -> 144 magnitudes; s = mean(log1p(mag)) = log(prod(1+mag))/144.
// out[b,p,e] = (s*u[e] + v[e]) * rsqrt(s^2*A + 2sB + C + eps) * gamma[e] + beta[e]
// ---------------------------------------------------------------------------

#define NPATCH 32768
#define EMBED 768
#define WROWS 129
#define EPS 1e-5f

__device__ float g_s[NPATCH];
__device__ __align__(16) float g_g1[EMBED];
__device__ __align__(16) float g_g2[EMBED];
__device__ float g_coef[4];

// ---------------------------------------------------------------------------
__device__ __forceinline__ float fsqrt_approx(float v) {
    float r;
    asm("sqrt.approx.f32 %0, %1;" : "=f"(r) : "f"(v));
    return r;
}

__device__ __forceinline__ float2 cmul(float2 a, float2 b) {
    return make_float2(fmaf(a.x, b.x, -a.y * b.y), fmaf(a.x, b.y, a.y * b.x));
}

// 16-point complex DIT FFT, fully unrolled, twiddles as immediates.
__device__ __forceinline__ void fft16(float2* a) {
    float2 t;
    t = a[1];  a[1]  = a[8];  a[8]  = t;
    t = a[2];  a[2]  = a[4];  a[4]  = t;
    t = a[3];  a[3]  = a[12]; a[12] = t;
    t = a[5];  a[5]  = a[10]; a[10] = t;
    t = a[7];  a[7]  = a[14]; a[14] = t;
    t = a[11]; a[11] = a[13]; a[13] = t;

    const float2 W16[8] = {
        { 1.0f,                  0.0f                 },
        { 0.92387953251128674f, -0.38268343236508978f },
        { 0.70710678118654757f, -0.70710678118654757f },
        { 0.38268343236508978f, -0.92387953251128674f },
        { 0.0f,                 -1.0f                 },
        {-0.38268343236508978f, -0.92387953251128674f },
        {-0.70710678118654757f, -0.70710678118654757f },
        {-0.92387953251128674f, -0.38268343236508978f },
    };

    #pragma unroll
    for (int s = 1; s <= 4; s++) {
        const int len  = 1 << s;
        const int half = len >> 1;
        const int step = 16 >> s;
        #pragma unroll
        for (int i = 0; i < 16; i += len) {
            #pragma unroll
            for (int j = 0; j < half; j++) {
                float2 w  = W16[j * step];
                float2 tt = cmul(w, a[i + j + half]);
                float2 u  = a[i + j];
                a[i + j]        = make_float2(u.x + tt.x, u.y + tt.y);
                a[i + j + half] = make_float2(u.x - tt.x, u.y - tt.y);
            }
        }
    }
}

// ---------------------------------------------------------------------------
// Kernel 1: per-patch scalar s.
// Block = 16 patches = contiguous 32x128 tile. Coalesced staged load.
// Phase 1: 128 threads, two-for-one real row FFTs (rows 2r, 2r+1 packed as
//          re+im of one complex FFT16, Hermitian unpack, 1/16 scale folded).
// Phase 2: 144 threads, column FFT16 + prod(1+mag), ONE log per thread.
// ---------------------------------------------------------------------------
__device__ __forceinline__ int sw_slot(int tr, int c) {
    return tr * 32 + ((c & 24) | ((c ^ tr) & 7));
}

__global__ __launch_bounds__(256, 4) void s_kernel(const float* __restrict__ x) {
    __shared__ float4 st[1024];          // staged 32x128 tile (swizzled)
    __shared__ float2 Z[16][9][17];      // row-FFT outputs [patch][k][row]
    __shared__ float  P[144];            // per-(patch,col) log partials

    const int tid = threadIdx.x;

    // ---- stage: perfectly coalesced tile load ----
    const float4* gx = reinterpret_cast<const float4*>(x) + (size_t)blockIdx.x * 1024;
    #pragma unroll
    for (int k = 0; k < 4; k++) {
        int g  = k * 256 + tid;
        int tr = g >> 5, c = g & 31;
        st[sw_slot(tr, c)] = gx[g];
    }
    __syncthreads();

    // ---- phase 1: two-for-one real row FFTs (threads 0..127) ----
    if (tid < 128) {
        const int lp  = tid >> 3;            // patch 0..15
        const int rr  = tid & 7;             // row pair 0..7
        const int tr0 = ((lp >> 3) << 4) + 2 * rr;
        const int w4  = (lp & 7) * 4;

        float2 z[16];
        #pragma unroll
        for (int i = 0; i < 4; i++) {
            float4 re = st[sw_slot(tr0,     w4 + i)];
            float4 im = st[sw_slot(tr0 + 1, w4 + i)];
            z[i * 4 + 0] = make_float2(re.x, im.x);
            z[i * 4 + 1] = make_float2(re.y, im.y);
            z[i * 4 + 2] = make_float2(re.z, im.z);
            z[i * 4 + 3] = make_float2(re.w, im.w);
        }
        fft16(z);

        // Hermitian unpack with ortho scale folded: h = 0.5 * (1/16)
        const float h = 0.03125f;
        #pragma unroll
        for (int k = 0; k < 9; k++) {
            const int m = (16 - k) & 15;
            float2 Zk = z[k], Zm = z[m];
            float2 Xa = make_float2(h * (Zk.x + Zm.x),  h * (Zk.y - Zm.y));
            float2 Xb = make_float2(h * (Zk.y + Zm.y), -h * (Zk.x - Zm.x));
            Z[lp][k][2 * rr]     = Xa;
            Z[lp][k][2 * rr + 1] = Xb;
        }
    }
    __syncthreads();

    // ---- phase 2: column FFTs + product of (1+mag), single log ----
    if (tid < 144) {
        const int p = tid / 9;
        const int k = tid - p * 9;
        float2 c[16];
        #pragma unroll
        for (int n = 0; n < 16; n++)
            c[n] = Z[p][k][n];
        fft16(c);

        float pr0 = 1.f, pr1 = 1.f;
        #pragma unroll
        for (int n = 0; n < 16; n += 2) {
            float m0 = fmaf(c[n].x,   c[n].x,   c[n].y   * c[n].y);
            float m1 = fmaf(c[n+1].x, c[n+1].x, c[n+1].y * c[n+1].y);
            pr0 *= (1.0f + fsqrt_approx(m0));
            pr1 *= (1.0f + fsqrt_approx(m1));
        }
        P[tid] = __logf(pr0 * pr1);
    }
    __syncthreads();

    // ---- per-patch final reduce ----
    if (tid < 16) {
        float s = 0.f;
        #pragma unroll
        for (int k = 0; k < 9; k++)
            s += P[tid * 9 + k];
        g_s[blockIdx.x * 16 + tid] = s * (1.0f / 144.0f);
    }
}

// ---------------------------------------------------------------------------
// Kernel 2: prep constants (single block, 768 threads)
// ---------------------------------------------------------------------------
__device__ __forceinline__ float block_sum768(float v, float* sh) {
    const int lane = threadIdx.x & 31;
    const int wid  = threadIdx.x >> 5;
    #pragma unroll
    for (int o = 16; o; o >>= 1)
        v += __shfl_xor_sync(0xffffffffu, v, o);
    __syncthreads();
    if (lane == 0) sh[wid] = v;
    __syncthreads();
    if (threadIdx.x == 0) {
        float tt = 0.f;
        #pragma unroll
        for (int i = 0; i < 24; i++) tt += sh[i];
        sh[24] = tt;
    }
    __syncthreads();
    return sh[24];
}

__global__ __launch_bounds__(768) void prep_kernel(const float* __restrict__ W,
                                                   const float* __restrict__ b,
                                                   const float* __restrict__ gamma) {
    __shared__ float sh[32];
    const int e = threadIdx.x;

    float wsum = 0.f;
    #pragma unroll 4
    for (int k = 0; k < WROWS; k++)
        wsum += W[k * EMBED + e];
    const float be = b[e];

    const float meanW = block_sum768(wsum, sh) * (1.0f / EMBED);
    const float meanb = block_sum768(be,   sh) * (1.0f / EMBED);

    const float u = wsum - meanW;
    const float v = be   - meanb;

    const float A = block_sum768(u * u, sh) * (1.0f / EMBED);
    const float B = block_sum768(u * v, sh) * (1.0f / EMBED);
    const float C = block_sum768(v * v, sh) * (1.0f / EMBED);

    g_g1[e] = u * gamma[e];
    g_g2[e] = v * gamma[e];
    if (e == 0) {
        g_coef[0] = A; g_coef[1] = B; g_coef[2] = C;
    }
}

// ---------------------------------------------------------------------------
// Kernel 3: output stream. 384 threads/block, 16 rows per block -> 2048 blocks.
// Each thread: one float4 column, 8 rows. Streaming stores of 100.7 MB.
// ---------------------------------------------------------------------------
__global__ __launch_bounds__(384) void out_kernel(const float* __restrict__ beta,
                                                  float4* __restrict__ out) {
    const int e4   = threadIdx.x % 192;
    const int rh   = threadIdx.x / 192;        // 0 or 1
    const int row0 = blockIdx.x * 16 + rh;

    const float4 G1 = reinterpret_cast<const float4*>(g_g1)[e4];
    const float4 G2 = reinterpret_cast<const float4*>(g_g2)[e4];
    const float4 BE = reinterpret_cast<const float4*>(beta)[e4];
    const float A = g_coef[0], B = g_coef[1], C = g_coef[2];

    #pragma unroll
    for (int r = 0; r < 8; r++) {
        const int row = row0 + 2 * r;
        const float s = g_s[row];
        const float inv = rsqrtf(fmaf(fmaf(A, s, 2.0f * B), s, C) + EPS);
        float4 o;
        o.x = fmaf(fmaf(s, G1.x, G2.x), inv, BE.x);
        o.y = fmaf(fmaf(s, G1.y, G2.y), inv, BE.y);
        o.z = fmaf(fmaf(s, G1.z, G2.z), inv, BE.z);
        o.w = fmaf(fmaf(s, G1.w, G2.w), inv, BE.w);
        __stcs(&out[(size_t)row * 192 + e4], o);
    }
}

// ---------------------------------------------------------------------------
extern "C" void kernel_launch(void* const* d_in, const int* in_sizes, int n_in,
                              void* d_out, int out_size) {
    const float* x     = (const float*)d_in[0];
    const float* W     = (const float*)d_in[1];
    const float* b     = (const float*)d_in[2];
    const float* gamma = (const float*)d_in[3];
    const float* beta  = (const float*)d_in[4];

    s_kernel<<<NPATCH / 16, 256>>>(x);
    prep_kernel<<<1, EMBED>>>(W, b, gamma);
    out_kernel<<<NPATCH / 16, 384>>>(beta, (float4*)d_out);
}